// round 3
// baseline (speedup 1.0000x reference)
#include <cuda_runtime.h>

#define B_   2048
#define T_   128
#define V_   256
#define H_   20
#define G3_  60
#define L_   15
#define NPAIR 8
#define NB    16               // batches per block (8 pairs)
#define NTHR  320              // tid = j*16 + s*8 + p ; 10 warps

typedef unsigned long long u64;

__device__ __forceinline__ u64 pk(float lo, float hi) {
    u64 r; asm("mov.b64 %0,{%1,%2};" : "=l"(r) : "f"(lo), "f"(hi)); return r;
}
__device__ __forceinline__ void upk(float& lo, float& hi, u64 v) {
    asm("mov.b64 {%0,%1},%2;" : "=f"(lo), "=f"(hi) : "l"(v));
}
__device__ __forceinline__ u64 f2fma(u64 a, u64 b, u64 c) {
    u64 d; asm("fma.rn.f32x2 %0,%1,%2,%3;" : "=l"(d) : "l"(a), "l"(b), "l"(c)); return d;
}

__device__ __forceinline__ float fsigm(float x) {
    return __fdividef(1.0f, 1.0f + __expf(-x));
}
__device__ __forceinline__ float ftanh_(float x) {
    float e = __expf(2.0f * x);
    return 1.0f - __fdividef(2.0f, e + 1.0f);
}

// butterfly-combine a packed accumulator with the s-partner (lane^8)
__device__ __forceinline__ void bfly(u64 acc, float& a, float& b) {
    float lo, hi; upk(lo, hi, acc);
    a = lo + __shfl_xor_sync(0xFFFFFFFFu, lo, 8);
    b = hi + __shfl_xor_sync(0xFFFFFFFFu, hi, 8);
}

__global__ __launch_bounds__(NTHR, 1)
void gru2_kernel(const int* __restrict__ x,
                 const float* __restrict__ W0, const float* __restrict__ U0,
                 const float* __restrict__ b0i, const float* __restrict__ b0r,
                 const float* __restrict__ W1, const float* __restrict__ U1,
                 const float* __restrict__ b1i, const float* __restrict__ b1r,
                 const float* __restrict__ Wd, const float* __restrict__ bd,
                 float* __restrict__ out)
{
    // layer0 weights: per (j,s) block of 32 u64: [g*10+kk], g in {z,r,h}, kk = k-half index
    __shared__ alignas(16) u64 Wsh0[H_ * 2 * 32];
    // layer1 weights: per (j,s) block of 64 u64: g in {Wz,Wr,Wh,Uz,Ur,Uh}
    __shared__ alignas(16) u64 Wsh1[H_ * 2 * 64];
    // hidden state (packed pairs). Row = 26 u64: s0 half at [0..9], s1 half at [12..21].
    // Row stride 208B -> 8 p start banks {0,20,8,28,16,4,24,12}: conflict-free LDS.128.
    __shared__ alignas(16) u64 h0buf[2][NPAIR][26];
    __shared__ alignas(16) u64 h1buf[2][NPAIR][26];
    __shared__ int   xs[NB][T_];
    __shared__ float lg[NB][L_];

    const int tid = threadIdx.x;
    const int p   = tid & 7;
    const int s   = (tid >> 3) & 1;
    const int j   = tid >> 4;            // 0..19
    const int bg  = blockIdx.x * NB;
    const int sj  = (j < 10) ? j : j + 2;   // slot of own j in h row

    // ---- setup: layer0 weights (dup-packed) ----
    for (int idx = tid; idx < H_ * 2 * 3 * 10; idx += NTHR) {
        int jj = idx / 60;
        int r  = idx % 60;
        int ss = r / 30;
        int r2 = r % 30;
        int g  = r2 / 10, kk = r2 % 10;
        int k  = ss * 10 + kk;
        float w = U0[k * G3_ + g * H_ + jj];
        Wsh0[(jj * 2 + ss) * 32 + g * 10 + kk] = pk(w, w);
    }
    // ---- layer1 weights ----
    for (int idx = tid; idx < H_ * 2 * 6 * 10; idx += NTHR) {
        int jj = idx / 120;
        int r  = idx % 120;
        int ss = r / 60;
        int r2 = r % 60;
        int g  = r2 / 10, kk = r2 % 10;
        int k  = ss * 10 + kk;
        float w = (g < 3) ? W1[k * G3_ + g * H_ + jj]
                          : U1[k * G3_ + (g - 3) * H_ + jj];
        Wsh1[(jj * 2 + ss) * 64 + g * 10 + kk] = pk(w, w);
    }
    // ---- x tokens ----
    for (int idx = tid; idx < NB * T_; idx += NTHR) {
        int bb = idx >> 7, t = idx & (T_ - 1);
        xs[bb][t] = x[(bg + bb) * T_ + t];
    }
    // ---- zero h ----
    {
        u64* hz0 = &h0buf[0][0][0];
        u64* hz1 = &h1buf[0][0][0];
        for (int idx = tid; idx < 2 * NPAIR * 26; idx += NTHR) { hz0[idx] = 0ull; hz1[idx] = 0ull; }
    }

    // bias registers
    const float bz0i = b0i[j], br0i = b0i[20 + j], bh0i = b0i[40 + j];
    const u64 zero2 = 0ull;
    const u64 bz0r2 = s == 0 ? pk(b0r[j], b0r[j]) : zero2;
    const u64 br0r2 = s == 0 ? pk(b0r[20 + j], b0r[20 + j]) : zero2;
    const u64 bh0r2 = s == 0 ? pk(b0r[40 + j], b0r[40 + j]) : zero2;
    const float bxz1 = b1i[j] + b1r[j];
    const float bxr1 = b1i[20 + j] + b1r[20 + j];
    const float bxh1 = b1i[40 + j];
    const float brh1 = b1r[40 + j];   // recurrent h-bias must stay inside r*(.) term
    __syncthreads();

    const ulonglong2* w0p = (const ulonglong2*)&Wsh0[(j * 2 + s) * 32];
    const ulonglong2* w1p = (const ulonglong2*)&Wsh1[(j * 2 + s) * 64];

    int cur = 0;
    for (int t = 0; t < T_; t++) {
        // -------- hoist W0 gather off the critical path --------
        const float* wA = W0 + xs[p][t] * G3_;
        const float* wB = W0 + xs[p + NPAIR][t] * G3_;
        float xwzA = wA[j],      xwzB = wB[j];
        float xwrA = wA[20 + j], xwrB = wB[20 + j];
        float xwhA = wA[40 + j], xwhB = wB[40 + j];

        // ================= layer 0: partial rec over own k-half =================
        const ulonglong2* hp = (const ulonglong2*)&h0buf[cur][p][s * 12];
        u64 az = bz0r2, ar = br0r2, ah = bh0r2;
        #pragma unroll
        for (int kk = 0; kk < 5; kk++) {
            ulonglong2 h2 = hp[kk];
            ulonglong2 z2 = w0p[kk], r2 = w0p[5 + kk], g2 = w0p[10 + kk];
            az = f2fma(h2.x, z2.x, az); az = f2fma(h2.y, z2.y, az);
            ar = f2fma(h2.x, r2.x, ar); ar = f2fma(h2.y, r2.y, ar);
            ah = f2fma(h2.x, g2.x, ah); ah = f2fma(h2.y, g2.y, ah);
        }
        float azA, azB, arA, arB, ahA, ahB;
        bfly(az, azA, azB);
        bfly(ar, arA, arB);
        bfly(ah, ahA, ahB);

        float zA = fsigm(xwzA + bz0i + azA);
        float zB = fsigm(xwzB + bz0i + azB);
        float rA = fsigm(xwrA + br0i + arA);
        float rB = fsigm(xwrB + br0i + arB);
        float gA = ftanh_(xwhA + bh0i + rA * ahA);
        float gB = ftanh_(xwhB + bh0i + rB * ahB);
        float hA, hB; upk(hA, hB, h0buf[cur][p][sj]);
        float h0nA = zA * hA + (1.0f - zA) * gA;
        float h0nB = zB * hB + (1.0f - zB) * gB;
        if (s == 0) h0buf[cur ^ 1][p][sj] = pk(h0nA, h0nB);
        __syncthreads();

        // ================= layer 1: partials over own k-half =================
        const ulonglong2* h0p = (const ulonglong2*)&h0buf[cur ^ 1][p][s * 12];
        const ulonglong2* h1p = (const ulonglong2*)&h1buf[cur][p][s * 12];
        u64 xz = zero2, xr = zero2, xh = zero2;
        u64 rz = zero2, rr = zero2, rh = zero2;
        #pragma unroll
        for (int kk = 0; kk < 5; kk++) {
            ulonglong2 a2 = h0p[kk];
            ulonglong2 b2 = h1p[kk];
            ulonglong2 wz2 = w1p[kk],      wr2 = w1p[5 + kk],  wh2 = w1p[10 + kk];
            ulonglong2 uz2 = w1p[15 + kk], ur2 = w1p[20 + kk], uh2 = w1p[25 + kk];
            xz = f2fma(a2.x, wz2.x, xz); xz = f2fma(a2.y, wz2.y, xz);
            xr = f2fma(a2.x, wr2.x, xr); xr = f2fma(a2.y, wr2.y, xr);
            xh = f2fma(a2.x, wh2.x, xh); xh = f2fma(a2.y, wh2.y, xh);
            rz = f2fma(b2.x, uz2.x, rz); rz = f2fma(b2.y, uz2.y, rz);
            rr = f2fma(b2.x, ur2.x, rr); rr = f2fma(b2.y, ur2.y, rr);
            rh = f2fma(b2.x, uh2.x, rh); rh = f2fma(b2.y, uh2.y, rh);
        }
        float xzA, xzB, xrA, xrB, xhA, xhB, rzA, rzB, rrA, rrB, rhA, rhB;
        bfly(xz, xzA, xzB); bfly(xr, xrA, xrB); bfly(xh, xhA, xhB);
        bfly(rz, rzA, rzB); bfly(rr, rrA, rrB); bfly(rh, rhA, rhB);

        float z1A = fsigm(xzA + rzA + bxz1);
        float z1B = fsigm(xzB + rzB + bxz1);
        float r1A = fsigm(xrA + rrA + bxr1);
        float r1B = fsigm(xrB + rrB + bxr1);
        float g1A = ftanh_(xhA + bxh1 + r1A * (rhA + brh1));
        float g1B = ftanh_(xhB + bxh1 + r1B * (rhB + brh1));
        float q1A, q1B; upk(q1A, q1B, h1buf[cur][p][sj]);
        float h1nA = z1A * q1A + (1.0f - z1A) * g1A;
        float h1nB = z1B * q1B + (1.0f - z1B) * g1B;
        if (s == 0) h1buf[cur ^ 1][p][sj] = pk(h1nA, h1nB);
        __syncthreads();
        cur ^= 1;
    }

    // ================= dense + softmax =================
    if (s == 0 && j < L_) {
        float accA = bd[j], accB = bd[j];
        #pragma unroll
        for (int k = 0; k < H_; k++) {
            float wdk = Wd[k * L_ + j];
            int slot = (k < 10) ? k : k + 2;
            float hl, hh; upk(hl, hh, h1buf[cur][p][slot]);
            accA = fmaf(hl, wdk, accA);
            accB = fmaf(hh, wdk, accB);
        }
        lg[p][j] = accA;
        lg[p + NPAIR][j] = accB;
    }
    __syncthreads();
    if (s == 0 && j < L_) {
        float mA = lg[p][0], mB = lg[p + NPAIR][0];
        #pragma unroll
        for (int l = 1; l < L_; l++) {
            mA = fmaxf(mA, lg[p][l]);
            mB = fmaxf(mB, lg[p + NPAIR][l]);
        }
        float sA = 0.f, sB = 0.f;
        #pragma unroll
        for (int l = 0; l < L_; l++) {
            sA += __expf(lg[p][l] - mA);
            sB += __expf(lg[p + NPAIR][l] - mB);
        }
        out[(bg + p) * L_ + j]         = __fdividef(__expf(lg[p][j] - mA), sA);
        out[(bg + p + NPAIR) * L_ + j] = __fdividef(__expf(lg[p + NPAIR][j] - mB), sB);
    }
}

extern "C" void kernel_launch(void* const* d_in, const int* in_sizes, int n_in,
                              void* d_out, int out_size)
{
    (void)in_sizes; (void)n_in; (void)out_size;
    const int*   x   = (const int*)  d_in[0];
    const float* W0  = (const float*)d_in[1];
    const float* U0  = (const float*)d_in[2];
    const float* b0i = (const float*)d_in[3];
    const float* b0r = (const float*)d_in[4];
    const float* W1  = (const float*)d_in[5];
    const float* U1  = (const float*)d_in[6];
    const float* b1i = (const float*)d_in[7];
    const float* b1r = (const float*)d_in[8];
    const float* Wd  = (const float*)d_in[9];
    const float* bd  = (const float*)d_in[10];
    float* out = (float*)d_out;

    gru2_kernel<<<B_ / NB, NTHR>>>(x, W0, U0, b0i, b0r, W1, U1, b1i, b1r, Wd, bd, out);
}

// round 5
// speedup vs baseline: 1.4863x; 1.4863x over previous
#include <cuda_runtime.h>

#define B_   2048
#define T_   128
#define V_   256
#define H_   20
#define G3_  60
#define L_   15
#define NPAIR 4
#define NB    8                 // batches per block (4 pairs)
#define NTHR  (NPAIR * H_)      // 80 threads: p = tid&3, j = tid>>2
#define WPAD  22                // u64 row stride (176B = 12 banks: conflict-free)

typedef unsigned long long u64;

__device__ __forceinline__ u64 pk(float lo, float hi) {
    u64 r; asm("mov.b64 %0,{%1,%2};" : "=l"(r) : "f"(lo), "f"(hi)); return r;
}
__device__ __forceinline__ void upk(float& lo, float& hi, u64 v) {
    asm("mov.b64 {%0,%1},%2;" : "=f"(lo), "=f"(hi) : "l"(v));
}
__device__ __forceinline__ u64 f2fma(u64 a, u64 b, u64 c) {
    u64 d; asm("fma.rn.f32x2 %0,%1,%2,%3;" : "=l"(d) : "l"(a), "l"(b), "l"(c)); return d;
}
__device__ __forceinline__ u64 f2add(u64 a, u64 b) {
    u64 d; asm("add.rn.f32x2 %0,%1,%2;" : "=l"(d) : "l"(a), "l"(b)); return d;
}

__device__ __forceinline__ float fsigm(float x) {
    return __fdividef(1.0f, 1.0f + __expf(-x));
}
__device__ __forceinline__ float ftanh_(float x) {
    float e = __expf(2.0f * x);
    return 1.0f - __fdividef(2.0f, e + 1.0f);
}

__global__ __launch_bounds__(NTHR, 2)
void gru2_kernel(const int* __restrict__ x,
                 const float* __restrict__ W0, const float* __restrict__ U0,
                 const float* __restrict__ b0i, const float* __restrict__ b0r,
                 const float* __restrict__ W1, const float* __restrict__ U1,
                 const float* __restrict__ b1i, const float* __restrict__ b1r,
                 const float* __restrict__ Wd, const float* __restrict__ bd,
                 float* __restrict__ out)
{
    // Dup-packed weights {w,w}: [gate][j][k(padded)], k contiguous.
    // Row stride WPAD u64 = 176B -> per-warp j starts hit distinct bank quads.
    __shared__ alignas(16) u64 U0d[3][H_][WPAD];
    __shared__ alignas(16) u64 W1d[3][H_][WPAD];
    __shared__ alignas(16) u64 U1d[3][H_][WPAD];
    // Packed hidden state: pair p holds batches (p, p+4); rows padded to 22 u64
    __shared__ alignas(16) u64 h0buf[2][NPAIR][WPAD];
    __shared__ alignas(16) u64 h1buf[2][NPAIR][WPAD];
    __shared__ int   xs[NB][T_];
    __shared__ float lg[NB][L_];

    const int tid = threadIdx.x;
    const int p   = tid & (NPAIR - 1);
    const int j   = tid >> 2;               // 0..19
    const int bg  = blockIdx.x * NB;

    // ---- setup: duplicate weights into shared ----
    for (int idx = tid; idx < 3 * H_ * H_; idx += NTHR) {
        int g = idx / (H_ * H_);
        int r = idx % (H_ * H_);
        int jj = r / H_, k = r % H_;
        float w0 = U0[k * G3_ + g * H_ + jj]; U0d[g][jj][k] = pk(w0, w0);
        float w1 = W1[k * G3_ + g * H_ + jj]; W1d[g][jj][k] = pk(w1, w1);
        float u1 = U1[k * G3_ + g * H_ + jj]; U1d[g][jj][k] = pk(u1, u1);
    }
    for (int idx = tid; idx < NB * T_; idx += NTHR) {
        int bb = idx >> 7, t = idx & (T_ - 1);
        xs[bb][t] = x[(bg + bb) * T_ + t];
    }
    h0buf[0][p][j] = 0ull; h0buf[1][p][j] = 0ull;
    h1buf[0][p][j] = 0ull; h1buf[1][p][j] = 0ull;

    // bias registers
    const float bz0i = b0i[j], br0i = b0i[20 + j], bh0i = b0i[40 + j];
    const u64   bz0r2 = pk(b0r[j], b0r[j]);
    const u64   br0r2 = pk(b0r[20 + j], b0r[20 + j]);
    const u64   bh0r2 = pk(b0r[40 + j], b0r[40 + j]);
    const u64   bz1i2 = pk(b1i[j], b1i[j]);
    const u64   br1i2 = pk(b1i[20 + j], b1i[20 + j]);
    const u64   bh1i2 = pk(b1i[40 + j], b1i[40 + j]);
    const u64   bz1r2 = pk(b1r[j], b1r[j]);
    const u64   br1r2 = pk(b1r[20 + j], b1r[20 + j]);
    const u64   bh1r2 = pk(b1r[40 + j], b1r[40 + j]);
    __syncthreads();

    const ulonglong2* wz = (const ulonglong2*)U0d[0][j];
    const ulonglong2* wr = (const ulonglong2*)U0d[1][j];
    const ulonglong2* wh = (const ulonglong2*)U0d[2][j];
    const ulonglong2* vz = (const ulonglong2*)W1d[0][j];
    const ulonglong2* vr = (const ulonglong2*)W1d[1][j];
    const ulonglong2* vh = (const ulonglong2*)W1d[2][j];
    const ulonglong2* uz = (const ulonglong2*)U1d[0][j];
    const ulonglong2* ur = (const ulonglong2*)U1d[1][j];
    const ulonglong2* uh = (const ulonglong2*)U1d[2][j];

    // prefetch W0 gather rows for t = 0
    float xwzA, xwzB, xwrA, xwrB, xwhA, xwhB;
    {
        const float* wA = W0 + xs[p][0] * G3_;
        const float* wB = W0 + xs[p + NPAIR][0] * G3_;
        xwzA = wA[j];      xwzB = wB[j];
        xwrA = wA[20 + j]; xwrB = wB[20 + j];
        xwhA = wA[40 + j]; xwhB = wB[40 + j];
    }

    int cur = 0;
    for (int t = 0; t < T_; t++) {
        // ================= layer 0: rec = h0 @ U0 (packed) =================
        const ulonglong2* hp = (const ulonglong2*)h0buf[cur][p];
        u64 az0 = bz0r2, az1 = 0ull;
        u64 ar0 = br0r2, ar1 = 0ull;
        u64 ah0 = bh0r2, ah1 = 0ull;
        #pragma unroll
        for (int kk = 0; kk < H_ / 2; kk++) {
            ulonglong2 h2 = hp[kk];
            ulonglong2 z2 = wz[kk], r2 = wr[kk], g2 = wh[kk];
            az0 = f2fma(h2.x, z2.x, az0); az1 = f2fma(h2.y, z2.y, az1);
            ar0 = f2fma(h2.x, r2.x, ar0); ar1 = f2fma(h2.y, r2.y, ar1);
            ah0 = f2fma(h2.x, g2.x, ah0); ah1 = f2fma(h2.y, g2.y, ah1);
        }
        float azA, azB, arA, arB, ahA, ahB;
        upk(azA, azB, f2add(az0, az1));
        upk(arA, arB, f2add(ar0, ar1));
        upk(ahA, ahB, f2add(ah0, ah1));

        float zA = fsigm(xwzA + bz0i + azA);
        float zB = fsigm(xwzB + bz0i + azB);
        float rA = fsigm(xwrA + br0i + arA);
        float rB = fsigm(xwrB + br0i + arB);
        float gA = ftanh_(xwhA + bh0i + rA * ahA);
        float gB = ftanh_(xwhB + bh0i + rB * ahB);
        float hA, hB; upk(hA, hB, h0buf[cur][p][j]);
        float h0nA = zA * hA + (1.0f - zA) * gA;
        float h0nB = zB * hB + (1.0f - zB) * gB;
        h0buf[cur ^ 1][p][j] = pk(h0nA, h0nB);
        __syncthreads();

        // -------- prefetch W0 gather for t+1 (consumed after next barrier) ----
        if (t + 1 < T_) {
            const float* wA = W0 + xs[p][t + 1] * G3_;
            const float* wB = W0 + xs[p + NPAIR][t + 1] * G3_;
            xwzA = wA[j];      xwzB = wB[j];
            xwrA = wA[20 + j]; xwrB = wB[20 + j];
            xwhA = wA[40 + j]; xwhB = wB[40 + j];
        }

        // ================= layer 1: xw = h0n @ W1, rec = h1 @ U1 =================
        const ulonglong2* h0p = (const ulonglong2*)h0buf[cur ^ 1][p];
        const ulonglong2* h1p = (const ulonglong2*)h1buf[cur][p];
        u64 xz = bz1i2, xr = br1i2, xh = bh1i2;
        u64 rz = bz1r2, rr = br1r2, rh = bh1r2;
        #pragma unroll
        for (int kk = 0; kk < H_ / 2; kk++) {
            ulonglong2 a2 = h0p[kk];
            ulonglong2 b2 = h1p[kk];
            ulonglong2 wz2 = vz[kk], wr2 = vr[kk], wh2 = vh[kk];
            ulonglong2 uz2 = uz[kk], ur2 = ur[kk], uh2 = uh[kk];
            xz = f2fma(a2.x, wz2.x, xz); xz = f2fma(a2.y, wz2.y, xz);
            xr = f2fma(a2.x, wr2.x, xr); xr = f2fma(a2.y, wr2.y, xr);
            xh = f2fma(a2.x, wh2.x, xh); xh = f2fma(a2.y, wh2.y, xh);
            rz = f2fma(b2.x, uz2.x, rz); rz = f2fma(b2.y, uz2.y, rz);
            rr = f2fma(b2.x, ur2.x, rr); rr = f2fma(b2.y, ur2.y, rr);
            rh = f2fma(b2.x, uh2.x, rh); rh = f2fma(b2.y, uh2.y, rh);
        }
        float xzA, xzB, xrA, xrB, xhA, xhB, rzA, rzB, rrA, rrB, rhA, rhB;
        upk(xzA, xzB, xz); upk(xrA, xrB, xr); upk(xhA, xhB, xh);
        upk(rzA, rzB, rz); upk(rrA, rrB, rr); upk(rhA, rhB, rh);
        float z1A = fsigm(xzA + rzA);
        float z1B = fsigm(xzB + rzB);
        float r1A = fsigm(xrA + rrA);
        float r1B = fsigm(xrB + rrB);
        float g1A = ftanh_(xhA + r1A * rhA);
        float g1B = ftanh_(xhB + r1B * rhB);
        float q1A, q1B; upk(q1A, q1B, h1buf[cur][p][j]);
        float h1nA = z1A * q1A + (1.0f - z1A) * g1A;
        float h1nB = z1B * q1B + (1.0f - z1B) * g1B;
        h1buf[cur ^ 1][p][j] = pk(h1nA, h1nB);
        __syncthreads();
        cur ^= 1;
    }

    // ================= dense + softmax (both batches per thread) =================
    if (j < L_) {
        float accA = bd[j], accB = bd[j];
        #pragma unroll
        for (int k = 0; k < H_; k++) {
            float wdk = Wd[k * L_ + j];
            float hl, hh; upk(hl, hh, h1buf[cur][p][k]);
            accA = fmaf(hl, wdk, accA);
            accB = fmaf(hh, wdk, accB);
        }
        lg[p][j] = accA;
        lg[p + NPAIR][j] = accB;
    }
    __syncthreads();
    if (j < L_) {
        float mA = lg[p][0], mB = lg[p + NPAIR][0];
        #pragma unroll
        for (int l = 1; l < L_; l++) {
            mA = fmaxf(mA, lg[p][l]);
            mB = fmaxf(mB, lg[p + NPAIR][l]);
        }
        float sA = 0.f, sB = 0.f;
        #pragma unroll
        for (int l = 0; l < L_; l++) {
            sA += __expf(lg[p][l] - mA);
            sB += __expf(lg[p + NPAIR][l] - mB);
        }
        out[(bg + p) * L_ + j]         = __fdividef(__expf(lg[p][j] - mA), sA);
        out[(bg + p + NPAIR) * L_ + j] = __fdividef(__expf(lg[p + NPAIR][j] - mB), sB);
    }
}

extern "C" void kernel_launch(void* const* d_in, const int* in_sizes, int n_in,
                              void* d_out, int out_size)
{
    (void)in_sizes; (void)n_in; (void)out_size;
    const int*   x   = (const int*)  d_in[0];
    const float* W0  = (const float*)d_in[1];
    const float* U0  = (const float*)d_in[2];
    const float* b0i = (const float*)d_in[3];
    const float* b0r = (const float*)d_in[4];
    const float* W1  = (const float*)d_in[5];
    const float* U1  = (const float*)d_in[6];
    const float* b1i = (const float*)d_in[7];
    const float* b1r = (const float*)d_in[8];
    const float* Wd  = (const float*)d_in[9];
    const float* bd  = (const float*)d_in[10];
    float* out = (float*)d_out;

    gru2_kernel<<<B_ / NB, NTHR>>>(x, W0, U0, b0i, b0r, W1, U1, b1i, b1r, Wd, bd, out);
}